// round 1
// baseline (speedup 1.0000x reference)
#include <cuda_runtime.h>
#include <math.h>

// Problem constants
constexpr int Bn = 4, Tn = 1024, DMn = 1024, Hn = 16, DKn = 64;
constexpr int BT = Bn * Tn;                 // 4096
constexpr int PLANE = BT * DMn;             // 4194304 elements
constexpr int NBH = Bn * Hn;                // 64 heads total

// ---------------- Scratch (device globals; allocation is forbidden) ----------
__device__ float g_Q[PLANE];
__device__ float g_K[PLANE];
__device__ float g_V[PLANE];
__device__ float g_Dre[2][PLANE];           // ping-pong real plane, (B,T,DM) layout
__device__ float g_Dim[2][PLANE];           // ping-pong imag plane
__device__ float g_A[(size_t)NBH * Tn * Tn];// adjacency, 268 MB
__device__ float g_gv[PLANE];               // gate * V, (B,T,DM)
__device__ float g_gate[(size_t)NBH * Tn * DKn]; // fallback gate target

// ---------------- Generic fp32 SGEMM: C = A(MxK) @ B(KxN), row-major ---------
// 64x64 tile, BK=16, 256 threads, 4x4 per thread.
__global__ void sgemm_nn_kernel(const float* __restrict__ A,
                                const float* __restrict__ B,
                                float* __restrict__ C,
                                int M, int N, int K) {
    __shared__ float As[64][17];   // padded: conflict-free column reads
    __shared__ float Bs[16][64];   // float4-aligned rows
    int tid = threadIdx.x;
    int tx = tid & 15, ty = tid >> 4;
    int m0 = blockIdx.y * 64, n0 = blockIdx.x * 64;

    float acc[4][4] = {};
    for (int k0 = 0; k0 < K; k0 += 16) {
        #pragma unroll
        for (int i = 0; i < 4; i++) {
            int l = tid + 256 * i;
            int r = l >> 4, c = l & 15;
            As[r][c] = A[(size_t)(m0 + r) * K + (k0 + c)];
        }
        #pragma unroll
        for (int i = 0; i < 4; i++) {
            int l = tid + 256 * i;
            int r = l >> 6, c = l & 63;
            Bs[r][c] = B[(size_t)(k0 + r) * N + (n0 + c)];
        }
        __syncthreads();
        #pragma unroll
        for (int kk = 0; kk < 16; kk++) {
            float a[4];
            #pragma unroll
            for (int i = 0; i < 4; i++) a[i] = As[ty * 4 + i][kk];
            float4 bv = *(const float4*)&Bs[kk][tx * 4];
            float b[4] = {bv.x, bv.y, bv.z, bv.w};
            #pragma unroll
            for (int i = 0; i < 4; i++)
                #pragma unroll
                for (int j = 0; j < 4; j++)
                    acc[i][j] = fmaf(a[i], b[j], acc[i][j]);
        }
        __syncthreads();
    }
    #pragma unroll
    for (int i = 0; i < 4; i++)
        #pragma unroll
        for (int j = 0; j < 4; j++)
            C[(size_t)(m0 + ty * 4 + i) * N + (n0 + tx * 4 + j)] = acc[i][j];
}

// ---------------- Scores: per head, S = (Q_h @ K_h^T) / 8 -------------------
// Q,K in (B,T,DM) layout; head slice stride DM. Output into g_A[bh].
__global__ void scores_nt_kernel(const float* __restrict__ Q,
                                 const float* __restrict__ Km,
                                 float* __restrict__ Aout) {
    int bh = blockIdx.z;
    int b = bh >> 4, h = bh & 15;
    const float* Ap = Q  + (size_t)b * Tn * DMn + h * DKn; // rows t, cols d (lda=DM)
    const float* Bp = Km + (size_t)b * Tn * DMn + h * DKn; // rows s, cols d
    float* Cp = Aout + (size_t)bh * Tn * Tn;

    __shared__ float As[64][17];
    __shared__ float Bs[16][68];   // 68*4=272 bytes/row: 16B-aligned rows, low conflicts
    int tid = threadIdx.x;
    int tx = tid & 15, ty = tid >> 4;
    int m0 = blockIdx.y * 64, n0 = blockIdx.x * 64;

    float acc[4][4] = {};
    for (int k0 = 0; k0 < DKn; k0 += 16) {
        #pragma unroll
        for (int i = 0; i < 4; i++) {
            int l = tid + 256 * i;
            int r = l >> 4, c = l & 15;
            As[r][c] = Ap[(size_t)(m0 + r) * DMn + (k0 + c)];
        }
        #pragma unroll
        for (int i = 0; i < 4; i++) {
            int l = tid + 256 * i;
            int n = l >> 4, k = l & 15;
            Bs[k][n] = Bp[(size_t)(n0 + n) * DMn + (k0 + k)];
        }
        __syncthreads();
        #pragma unroll
        for (int kk = 0; kk < 16; kk++) {
            float a[4];
            #pragma unroll
            for (int i = 0; i < 4; i++) a[i] = As[ty * 4 + i][kk];
            float4 bv = *(const float4*)&Bs[kk][tx * 4];
            float b[4] = {bv.x, bv.y, bv.z, bv.w};
            #pragma unroll
            for (int i = 0; i < 4; i++)
                #pragma unroll
                for (int j = 0; j < 4; j++)
                    acc[i][j] = fmaf(a[i], b[j], acc[i][j]);
        }
        __syncthreads();
    }
    #pragma unroll
    for (int i = 0; i < 4; i++)
        #pragma unroll
        for (int j = 0; j < 4; j++)
            Cp[(size_t)(m0 + ty * 4 + i) * Tn + (n0 + tx * 4 + j)] = acc[i][j] * 0.125f;
}

// ---------------- Row softmax over last axis of A (65536 rows of 1024) ------
__global__ void softmax_rows_kernel(float* __restrict__ A) {
    float* p = A + (size_t)blockIdx.x * Tn;
    int tid = threadIdx.x;  // 256
    float v[4];
    float mx = -1e30f;
    #pragma unroll
    for (int i = 0; i < 4; i++) { v[i] = p[tid + 256 * i]; mx = fmaxf(mx, v[i]); }

    __shared__ float red[8];
    #pragma unroll
    for (int o = 16; o; o >>= 1) mx = fmaxf(mx, __shfl_xor_sync(0xffffffffu, mx, o));
    if ((tid & 31) == 0) red[tid >> 5] = mx;
    __syncthreads();
    if (tid == 0) {
        float m = red[0];
        #pragma unroll
        for (int i = 1; i < 8; i++) m = fmaxf(m, red[i]);
        red[0] = m;
    }
    __syncthreads();
    mx = red[0];
    __syncthreads();

    float s = 0.f;
    #pragma unroll
    for (int i = 0; i < 4; i++) { v[i] = expf(v[i] - mx); s += v[i]; }
    #pragma unroll
    for (int o = 16; o; o >>= 1) s += __shfl_xor_sync(0xffffffffu, s, o);
    if ((tid & 31) == 0) red[tid >> 5] = s;
    __syncthreads();
    if (tid == 0) {
        float m = 0.f;
        #pragma unroll
        for (int i = 0; i < 8; i++) m += red[i];
        red[0] = m;
    }
    __syncthreads();
    float inv = 1.f / red[0];
    #pragma unroll
    for (int i = 0; i < 4; i++) p[tid + 256 * i] = v[i] * inv;
}

// ---------------- Propagation: Dout = (1-lam)*Din + lam * (A @ Din) ---------
// batch z in [0,128): b = z>>5, h = (z>>1)&15, plane = z&1 (0=re, 1=im).
// A head (1024x1024), Din/Dout head slice in (B,T,DM), ldb = DM.
__global__ void prop_nn_kernel(const float* __restrict__ Abase,
                               const float* __restrict__ DinRe,
                               const float* __restrict__ DinIm,
                               float* __restrict__ DoutRe,
                               float* __restrict__ DoutIm,
                               const float* __restrict__ lam_ptr) {
    int z = blockIdx.z;
    int b = z >> 5, h = (z >> 1) & 15, plane = z & 1;
    const float* Am = Abase + (size_t)(b * Hn + h) * Tn * Tn;
    const float* Din = (plane ? DinIm : DinRe) + (size_t)b * Tn * DMn + h * DKn;
    float* Dout = (plane ? DoutIm : DoutRe) + (size_t)b * Tn * DMn + h * DKn;

    float lam = 1.f / (1.f + expf(-lam_ptr[0]));
    float oml = 1.f - lam;

    __shared__ float As[64][17];
    __shared__ float Bs[16][64];
    int tid = threadIdx.x;
    int tx = tid & 15, ty = tid >> 4;
    int m0 = blockIdx.y * 64;   // N = 64 exactly, single column tile

    float acc[4][4] = {};
    for (int k0 = 0; k0 < Tn; k0 += 16) {
        #pragma unroll
        for (int i = 0; i < 4; i++) {
            int l = tid + 256 * i;
            int r = l >> 4, c = l & 15;
            As[r][c] = Am[(size_t)(m0 + r) * Tn + (k0 + c)];
        }
        #pragma unroll
        for (int i = 0; i < 4; i++) {
            int l = tid + 256 * i;
            int r = l >> 6, c = l & 63;
            Bs[r][c] = Din[(size_t)(k0 + r) * DMn + c];
        }
        __syncthreads();
        #pragma unroll
        for (int kk = 0; kk < 16; kk++) {
            float a[4];
            #pragma unroll
            for (int i = 0; i < 4; i++) a[i] = As[ty * 4 + i][kk];
            float4 bv = *(const float4*)&Bs[kk][tx * 4];
            float b2[4] = {bv.x, bv.y, bv.z, bv.w};
            #pragma unroll
            for (int i = 0; i < 4; i++)
                #pragma unroll
                for (int j = 0; j < 4; j++)
                    acc[i][j] = fmaf(a[i], b2[j], acc[i][j]);
        }
        __syncthreads();
    }
    #pragma unroll
    for (int i = 0; i < 4; i++) {
        int row = m0 + ty * 4 + i;
        #pragma unroll
        for (int j = 0; j < 4; j++) {
            int col = tx * 4 + j;
            float din = Din[(size_t)row * DMn + col];
            Dout[(size_t)row * DMn + col] = oml * din + lam * acc[i][j];
        }
    }
}

// ---------------- Readout: mean field, gate softmax over T, gated V ---------
// One block per (b,h). 256 threads: d = tid&63, group g = tid>>6 strides t.
__global__ void readout_kernel(const float* __restrict__ Dre,
                               const float* __restrict__ Dim,
                               const float* __restrict__ V,
                               float* __restrict__ gate,
                               float* __restrict__ gv) {
    int bh = blockIdx.x;
    int b = bh >> 4, h = bh & 15;
    const size_t base = (size_t)b * Tn * DMn + h * DKn;
    int tid = threadIdx.x;
    int d = tid & 63, g = tid >> 6;

    __shared__ float s_a[4][64], s_b[4][64];
    __shared__ float s_mre[64], s_mim[64], s_mn[64];

    // 1. mean over T
    float sre = 0.f, sim = 0.f;
    for (int t = g; t < Tn; t += 4) {
        size_t idx = base + (size_t)t * DMn + d;
        sre += Dre[idx];
        sim += Dim[idx];
    }
    s_a[g][d] = sre; s_b[g][d] = sim;
    __syncthreads();
    if (g == 0) {
        float mre = (s_a[0][d] + s_a[1][d] + s_a[2][d] + s_a[3][d]) * (1.f / Tn);
        float mim = (s_b[0][d] + s_b[1][d] + s_b[2][d] + s_b[3][d]) * (1.f / Tn);
        s_mre[d] = mre; s_mim[d] = mim;
        s_mn[d] = sqrtf(mre * mre + mim * mim);
    }
    __syncthreads();
    float mre = s_mre[d], mim = s_mim[d], mn = s_mn[d];

    // 2. column max of cosine score
    float mx = -1e30f;
    for (int t = g; t < Tn; t += 4) {
        size_t idx = base + (size_t)t * DMn + d;
        float re = Dre[idx], im = Dim[idx];
        float dot = re * mre + im * mim;
        float nrm = sqrtf(re * re + im * im) * mn + 1e-8f;
        mx = fmaxf(mx, dot / nrm);
    }
    __syncthreads();
    s_a[g][d] = mx;
    __syncthreads();
    float cmx = fmaxf(fmaxf(s_a[0][d], s_a[1][d]), fmaxf(s_a[2][d], s_a[3][d]));
    __syncthreads();

    // 3. column sum of exp
    float ssum = 0.f;
    for (int t = g; t < Tn; t += 4) {
        size_t idx = base + (size_t)t * DMn + d;
        float re = Dre[idx], im = Dim[idx];
        float dot = re * mre + im * mim;
        float nrm = sqrtf(re * re + im * im) * mn + 1e-8f;
        ssum += expf(dot / nrm - cmx);
    }
    s_a[g][d] = ssum;
    __syncthreads();
    float csum = s_a[0][d] + s_a[1][d] + s_a[2][d] + s_a[3][d];
    float inv = 1.f / csum;

    // 4. gate + gated V
    for (int t = g; t < Tn; t += 4) {
        size_t idx = base + (size_t)t * DMn + d;
        float re = Dre[idx], im = Dim[idx];
        float dot = re * mre + im * mim;
        float nrm = sqrtf(re * re + im * im) * mn + 1e-8f;
        float gt = expf(dot / nrm - cmx) * inv;
        gate[((size_t)bh * Tn + t) * DKn + d] = gt;
        gv[idx] = gt * V[idx];
    }
}

// ---------------- Launch -----------------------------------------------------
extern "C" void kernel_launch(void* const* d_in, const int* in_sizes, int n_in,
                              void* d_out, int out_size) {
    const float* x    = (const float*)d_in[0];
    const float* W_Q  = (const float*)d_in[1];
    const float* W_K  = (const float*)d_in[2];
    const float* W_re = (const float*)d_in[3];
    const float* W_im = (const float*)d_in[4];
    const float* W_V  = (const float*)d_in[5];
    const float* W_O  = (const float*)d_in[6];
    const float* lam  = (const float*)d_in[7];

    float *Q, *Kb, *V, *DreB, *DimB, *Ab, *gv, *gateScratch;
    cudaGetSymbolAddress((void**)&Q, g_Q);
    cudaGetSymbolAddress((void**)&Kb, g_K);
    cudaGetSymbolAddress((void**)&V, g_V);
    cudaGetSymbolAddress((void**)&DreB, g_Dre);
    cudaGetSymbolAddress((void**)&DimB, g_Dim);
    cudaGetSymbolAddress((void**)&Ab, g_A);
    cudaGetSymbolAddress((void**)&gv, g_gv);
    cudaGetSymbolAddress((void**)&gateScratch, g_gate);

    float* Dre0 = DreB;           float* Dre1 = DreB + PLANE;
    float* Dim0 = DimB;           float* Dim1 = DimB + PLANE;

    float* out = (float*)d_out;
    float* gate_dst = (out_size >= 2 * PLANE) ? out + PLANE : gateScratch;

    dim3 thr(256);
    dim3 gemm_grid(DMn / 64, BT / 64);   // (16, 64)

    // Projections
    sgemm_nn_kernel<<<gemm_grid, thr>>>(x, W_Q,  Q,     BT, DMn, DMn);
    sgemm_nn_kernel<<<gemm_grid, thr>>>(x, W_K,  Kb,    BT, DMn, DMn);
    sgemm_nn_kernel<<<gemm_grid, thr>>>(x, W_re, Dre0,  BT, DMn, DMn);
    sgemm_nn_kernel<<<gemm_grid, thr>>>(x, W_im, Dim0,  BT, DMn, DMn);
    sgemm_nn_kernel<<<gemm_grid, thr>>>(x, W_V,  V,     BT, DMn, DMn);

    // Adjacency
    scores_nt_kernel<<<dim3(Tn / 64, Tn / 64, NBH), thr>>>(Q, Kb, Ab);
    softmax_rows_kernel<<<NBH * Tn, thr>>>(Ab);

    // Topology propagation (3 steps, ping-pong)
    dim3 prop_grid(1, Tn / 64, NBH * 2);   // (1, 16, 128)
    prop_nn_kernel<<<prop_grid, thr>>>(Ab, Dre0, Dim0, Dre1, Dim1, lam);
    prop_nn_kernel<<<prop_grid, thr>>>(Ab, Dre1, Dim1, Dre0, Dim0, lam);
    prop_nn_kernel<<<prop_grid, thr>>>(Ab, Dre0, Dim0, Dre1, Dim1, lam);

    // Collapse readout + gating
    readout_kernel<<<NBH, thr>>>(Dre1, Dim1, V, gate_dst, gv);

    // Output projection
    sgemm_nn_kernel<<<gemm_grid, thr>>>(gv, W_O, out, BT, DMn, DMn);
}